// round 3
// baseline (speedup 1.0000x reference)
#include <cuda_runtime.h>
#include <cuda_bf16.h>

#define NTOK 25
#define DIM  128
#define NH   4
#define HD   32
#define NWIN 64
#define WSQ  49

// Transposed weight scratch (filled each launch by a prologue kernel).
__device__ float g_wT[DIM * 3 * DIM];   // [k][j]  j in [0,384)
__device__ float g_pT[DIM * DIM];       // [k][j]  j in [0,128)

__global__ void transpose_weights(const float* __restrict__ qkv_w,
                                  const float* __restrict__ proj_w)
{
    const int e = blockIdx.x * 256 + threadIdx.x;
    if (e < 3 * DIM * DIM) {
        const int j = e / DIM, kk = e % DIM;
        g_wT[kk * (3 * DIM) + j] = qkv_w[e];
    }
    if (e < DIM * DIM) {
        const int j = e / DIM, kk = e % DIM;
        g_pT[kk * DIM + j] = proj_w[e];
    }
}

typedef unsigned long long u64t;

__device__ __forceinline__ u64t pack2(float lo, float hi) {
    u64t r; asm("mov.b64 %0, {%1, %2};" : "=l"(r) : "f"(lo), "f"(hi)); return r;
}
__device__ __forceinline__ float2 unpack2(u64t v) {
    float2 r; asm("mov.b64 {%0, %1}, %2;" : "=f"(r.x), "=f"(r.y) : "l"(v)); return r;
}
#define FMA2(d, a, b, c) \
    asm("fma.rn.f32x2 %0, %1, %2, %3;" : "=l"(d) : "l"(a), "l"(b), "l"(c))
#define ADD2(d, a, b) \
    asm("add.rn.f32x2 %0, %1, %2;" : "=l"(d) : "l"(a), "l"(b))

// Shared layout (floats):
//   xT/oT [128][28]          0 .. 3584     (x transposed; later proj input oT[c][n])
//   qs    [h][n][36]      3584 .. 7184     (pre-scaled q, row-major per token)
//   ks    [h][m][36]      7184 .. 10784
//   vs    [h][m][36]     10784 .. 14384
//   at    [h][n][26]     14384 .. 16984    (bias+mask tile)
//   ids   (25 ints)      16984 ..
#define OFF_Q  3584
#define OFF_K  7184
#define OFF_V  10784
#define OFF_AT 14384
#define OFF_ID 16984
#define SM_FLOATS 17016

__global__ __launch_bounds__(256, 2)
void win_attn_kernel(const float* __restrict__ x,
                     const float* __restrict__ mask,
                     const int*   __restrict__ ids_keep,
                     const float* __restrict__ qkv_b,
                     const float* __restrict__ proj_b,
                     const float* __restrict__ bias_table,
                     const int*   __restrict__ rel_index,
                     float* __restrict__ out)
{
    extern __shared__ float sm[];
    float* xT = sm;
    float* qs = sm + OFF_Q;
    float* ks = sm + OFF_K;
    float* vs = sm + OFF_V;
    float* at = sm + OFF_AT;
    int*  ids = (int*)(sm + OFF_ID);

    const int b = blockIdx.x;
    const int w = b & (NWIN - 1);
    const int t = threadIdx.x;

    // ---- P0: load x (transposed, pad 28) + ids ----
    const float* xb = x + (size_t)b * (NTOK * DIM);
    for (int e = t; e < NTOK * DIM; e += 256) {
        const int i = e >> 7, kk = e & 127;
        xT[kk * 28 + i] = xb[e];
    }
    if (t < NTOK) ids[t] = ids_keep[w * NTOK + t];
    __syncthreads();

    // ---- P1a (t<192): QKV gemm, 2 cols per thread ----
    if (t < 192) {
        const int j0 = 2 * t;
        u64t acc_a[12], acc_b[12];
        float a24, b24;
        {
            const float bja = qkv_b[j0], bjb = qkv_b[j0 + 1];
            #pragma unroll
            for (int p = 0; p < 12; p++) { acc_a[p] = pack2(bja, bja); acc_b[p] = pack2(bjb, bjb); }
            a24 = bja; b24 = bjb;
        }
        #pragma unroll 2
        for (int kk = 0; kk < DIM; kk++) {
            const float2 wv = *(const float2*)(g_wT + kk * 384 + j0);
            const u64t w2a = pack2(wv.x, wv.x);
            const u64t w2b = pack2(wv.y, wv.y);
            const float* xr = xT + kk * 28;
            const ulonglong2* xr2 = (const ulonglong2*)xr;
            #pragma unroll
            for (int p6 = 0; p6 < 6; p6++) {
                const ulonglong2 xv = xr2[p6];              // LDS.128 broadcast
                FMA2(acc_a[2 * p6],     xv.x, w2a, acc_a[2 * p6]);
                FMA2(acc_a[2 * p6 + 1], xv.y, w2a, acc_a[2 * p6 + 1]);
                FMA2(acc_b[2 * p6],     xv.x, w2b, acc_b[2 * p6]);
                FMA2(acc_b[2 * p6 + 1], xv.y, w2b, acc_b[2 * p6 + 1]);
            }
            const float x24 = xr[24];
            a24 = fmaf(x24, wv.x, a24);
            b24 = fmaf(x24, wv.y, b24);
        }
        // store pairs (d0, d0+1) row-major with stride 36
        const int part = j0 >> 7, jj = j0 & 127, h = jj >> 5, d0 = jj & 31;
        float* base = (part == 0 ? qs : part == 1 ? ks : vs) + h * 900 + d0;
        const float scale = (part == 0) ? 0.17677669529663687f : 1.0f;
        #pragma unroll
        for (int p = 0; p < 12; p++) {
            const float2 ua = unpack2(acc_a[p]);
            const float2 ub = unpack2(acc_b[p]);
            *(float2*)(base + (2 * p) * 36)     = make_float2(ua.x * scale, ub.x * scale);
            *(float2*)(base + (2 * p + 1) * 36) = make_float2(ua.y * scale, ub.y * scale);
        }
        *(float2*)(base + 24 * 36) = make_float2(a24 * scale, b24 * scale);
    }
    // ---- P1b (t>=192): bias+mask precompute into at[] (independent of QKV) ----
    else {
        const float* mrow = mask + w * (WSQ * WSQ);
        for (int e = t - 192; e < NH * NTOK * NTOK; e += 64) {
            const int h = e / (NTOK * NTOK);
            const int r = e - h * (NTOK * NTOK);
            const int n = r / NTOK, m = r - n * NTOK;
            const int in_ = ids[n], im = ids[m];
            const int ridx = rel_index[in_ * WSQ + im];
            at[(h * NTOK + n) * 26 + m] =
                bias_table[ridx * NH + h] + mrow[in_ * WSQ + im];
        }
    }
    __syncthreads();

    // ---- P2 (t<128): scores + softmax + attn@V, warp=head, lane=token ----
    if (t < 128) {
        const int h = t >> 5, n = t & 31;
        if (n < NTOK) {
            // q row -> registers (16 packed pairs)
            ulonglong2 q8[8];
            const ulonglong2* qr = (const ulonglong2*)(qs + (h * NTOK + n) * 36);
            #pragma unroll
            for (int p = 0; p < 8; p++) q8[p] = qr[p];

            float r[NTOK];
            #pragma unroll
            for (int m = 0; m < NTOK; m++) {
                const ulonglong2* kr = (const ulonglong2*)(ks + (h * NTOK + m) * 36);
                u64t a0 = 0, a1 = 0, a2 = 0, a3 = 0;
                #pragma unroll
                for (int p = 0; p < 8; p += 2) {
                    const ulonglong2 kv0 = kr[p];
                    FMA2(a0, q8[p].x, kv0.x, a0);
                    FMA2(a1, q8[p].y, kv0.y, a1);
                    const ulonglong2 kv1 = kr[p + 1];
                    FMA2(a2, q8[p + 1].x, kv1.x, a2);
                    FMA2(a3, q8[p + 1].y, kv1.y, a3);
                }
                ADD2(a0, a0, a2);
                ADD2(a1, a1, a3);
                ADD2(a0, a0, a1);
                const float2 u = unpack2(a0);
                r[m] = u.x + u.y;
            }
            // + bias + mask
            const float* bmrow = at + (h * NTOK + n) * 26;
            #pragma unroll
            for (int p = 0; p < 12; p++) {
                const float2 bv = *(const float2*)(bmrow + 2 * p);
                r[2 * p] += bv.x; r[2 * p + 1] += bv.y;
            }
            r[24] += bmrow[24];
            // softmax in registers
            float mx = r[0];
            #pragma unroll
            for (int m = 1; m < NTOK; m++) mx = fmaxf(mx, r[m]);
            float s = 0.f;
            #pragma unroll
            for (int m = 0; m < NTOK; m++) { r[m] = __expf(r[m] - mx); s += r[m]; }
            const float inv = 1.0f / s;
            #pragma unroll
            for (int m = 0; m < NTOK; m++) r[m] *= inv;
            // attn @ V
            u64t o2[16];
            #pragma unroll
            for (int p = 0; p < 16; p++) o2[p] = 0;
            #pragma unroll
            for (int m = 0; m < NTOK; m++) {
                const ulonglong2* vr = (const ulonglong2*)(vs + (h * NTOK + m) * 36);
                const u64t pm = pack2(r[m], r[m]);
                #pragma unroll
                for (int p = 0; p < 8; p++) {
                    const ulonglong2 vv = vr[p];
                    FMA2(o2[2 * p],     vv.x, pm, o2[2 * p]);
                    FMA2(o2[2 * p + 1], vv.y, pm, o2[2 * p + 1]);
                }
            }
            // store transposed: oT[c][n], c = h*32 + d  (coalesced over lanes)
            float* ob = xT + (h * HD) * 28 + n;
            #pragma unroll
            for (int p = 0; p < 16; p++) {
                const float2 u = unpack2(o2[p]);
                ob[(2 * p) * 28]     = u.x;
                ob[(2 * p + 1) * 28] = u.y;
            }
        }
    }
    __syncthreads();

    // ---- P3 (t<128): proj gemm, 1 col per thread ----
    if (t < DIM) {
        const int j = t;
        u64t acc[12];
        float a24;
        {
            const float pb = proj_b[j];
            #pragma unroll
            for (int p = 0; p < 12; p++) acc[p] = pack2(pb, pb);
            a24 = pb;
        }
        #pragma unroll 2
        for (int c = 0; c < DIM; c++) {
            const float wv = g_pT[c * DIM + j];
            const u64t w2 = pack2(wv, wv);
            const float* orow = xT + c * 28;
            const ulonglong2* orow2 = (const ulonglong2*)orow;
            #pragma unroll
            for (int p6 = 0; p6 < 6; p6++) {
                const ulonglong2 ov = orow2[p6];
                FMA2(acc[2 * p6],     ov.x, w2, acc[2 * p6]);
                FMA2(acc[2 * p6 + 1], ov.y, w2, acc[2 * p6 + 1]);
            }
            a24 = fmaf(orow[24], wv, a24);
        }
        float* ob = out + (size_t)b * (NTOK * DIM) + j;
        #pragma unroll
        for (int p = 0; p < 12; p++) {
            const float2 v = unpack2(acc[p]);
            ob[(2 * p) * DIM]     = v.x;
            ob[(2 * p + 1) * DIM] = v.y;
        }
        ob[24 * DIM] = a24;
    }
}

extern "C" void kernel_launch(void* const* d_in, const int* in_sizes, int n_in,
                              void* d_out, int out_size)
{
    const float* x          = (const float*)d_in[0];
    const float* mask       = (const float*)d_in[1];
    const int*   ids_keep   = (const int*)  d_in[2];
    const float* qkv_w      = (const float*)d_in[3];
    const float* qkv_b      = (const float*)d_in[4];
    const float* proj_w     = (const float*)d_in[5];
    const float* proj_b     = (const float*)d_in[6];
    const float* bias_table = (const float*)d_in[7];
    const int*   rel_index  = (const int*)  d_in[8];

    transpose_weights<<<(3 * DIM * DIM + 255) / 256, 256>>>(qkv_w, proj_w);

    const int smem_bytes = SM_FLOATS * 4;
    cudaFuncSetAttribute(win_attn_kernel,
                         cudaFuncAttributeMaxDynamicSharedMemorySize, smem_bytes);
    win_attn_kernel<<<4096, 256, smem_bytes>>>(
        x, mask, ids_keep, qkv_b, proj_b, bias_table, rel_index, (float*)d_out);
}

// round 5
// speedup vs baseline: 2.1866x; 2.1866x over previous
#include <cuda_runtime.h>
#include <cstdint>

#define NTOK 25
#define DIM  128
#define NH   4
#define NWIN 64
#define WSQ  49

typedef unsigned long long u64t;

// Weight fragments, tf32-converted (hi only), B-frag order (float4 = 2 k-steps).
__device__ float4 g_bqkv[48 * 8 * 32];   // [nt(48)][ks2(8)][lane(32)]
__device__ float4 g_bproj[16 * 8 * 32];  // [nt(16)][ks2(8)][lane(32)]

__device__ __forceinline__ uint32_t to_tf32(float f) {
    uint32_t u; asm("cvt.rna.tf32.f32 %0, %1;" : "=r"(u) : "f"(f)); return u;
}
__device__ __forceinline__ float tf32f(float f) { return __uint_as_float(to_tf32(f)); }

__global__ void pack_weights(const float* __restrict__ qkv_w,
                             const float* __restrict__ proj_w)
{
    const int p = blockIdx.x * 256 + threadIdx.x;     // 64 x 256 = 16384
    const int l = p & 31;
    const int ks2 = (p >> 5) & 7;
    if (p < 48 * 8 * 32) {
        const int nt = p >> 8;
        const int n = nt * 8 + (l >> 2);
        const int k = ks2 * 16 + (l & 3);
        const float* wr = qkv_w + n * DIM + k;
        g_bqkv[p] = make_float4(tf32f(wr[0]), tf32f(wr[4]), tf32f(wr[8]), tf32f(wr[12]));
    } else {
        const int q = p - 48 * 8 * 32;
        const int nt = q >> 8;
        const int n = nt * 8 + (l >> 2);
        const int k = ks2 * 16 + (l & 3);
        const float* wr = proj_w + n * DIM + k;
        g_bproj[q] = make_float4(tf32f(wr[0]), tf32f(wr[4]), tf32f(wr[8]), tf32f(wr[12]));
    }
}

#define MMA_TF32(Cv, a0, a1, a2, a3, b0, b1)                          \
    asm("mma.sync.aligned.m16n8k8.row.col.f32.tf32.tf32.f32 "          \
        "{%0,%1,%2,%3}, {%4,%5,%6,%7}, {%8,%9}, {%0,%1,%2,%3};"        \
        : "+f"(Cv[0]), "+f"(Cv[1]), "+f"(Cv[2]), "+f"(Cv[3])           \
        : "r"(a0), "r"(a1), "r"(a2), "r"(a3), "r"(b0), "r"(b1))

__device__ __forceinline__ u64t pack2(float lo, float hi) {
    u64t r; asm("mov.b64 %0, {%1, %2};" : "=l"(r) : "f"(lo), "f"(hi)); return r;
}
__device__ __forceinline__ float2 unpack2(u64t v) {
    float2 r; asm("mov.b64 {%0, %1}, %2;" : "=f"(r.x), "=f"(r.y) : "l"(v)); return r;
}
#define FMA2(d, a, b, c) \
    asm("fma.rn.f32x2 %0, %1, %2, %3;" : "=l"(d) : "l"(a), "l"(b), "l"(c))
#define ADD2(d, a, b) \
    asm("add.rn.f32x2 %0, %1, %2;" : "=l"(d) : "l"(a), "l"(b))

// Shared layout (floats):
//   af_hi [0, 5120)         A-frags hi (1024 pos x stride 5)
//   af_lo [5120, 10240)     A-frags lo
//   qs/ks/vs [10240, 21040) [part][h][tok][36]
//   ids at 21040
#define OFF_ALO 5120
#define OFF_QKV 10240
#define OFF_IDS 21040
#define SM_FLOATS 21072

__global__ __launch_bounds__(256, 2)
void win_attn_kernel(const float* __restrict__ x,
                     const float* __restrict__ mask,
                     const int*   __restrict__ ids_keep,
                     const float* __restrict__ qkv_b,
                     const float* __restrict__ proj_b,
                     const float* __restrict__ bias_table,
                     const int*   __restrict__ rel_index,
                     float* __restrict__ out)
{
    extern __shared__ float sm[];
    float* afh = sm;
    float* afl = sm + OFF_ALO;
    int* ids = (int*)(sm + OFF_IDS);

    const int b = blockIdx.x;
    const int w = b & (NWIN - 1);
    const int t = threadIdx.x;
    const int wid = t >> 5, lane = t & 31;
    const int g = lane >> 2, qd = lane & 3;

    // ---- P0: pack x into A-frag hi/lo layout, rows >= 25 zeroed ----
    {
        const float* xb = x + (size_t)b * (NTOK * DIM);
        #pragma unroll
        for (int i = 0; i < 4; i++) {
            const int pos = t + 256 * i;
            const int l = pos & 31, ksv = (pos >> 5) & 15, mt = pos >> 9;
            const int r0 = mt * 16 + (l >> 2);
            const int c0 = ksv * 8 + (l & 3);
            const float* xp = xb + r0 * DIM + c0;
            const float x0 = xp[0], x2 = xp[4];
            float x1 = 0.f, x3 = 0.f;
            if (r0 + 8 < NTOK) { x1 = xp[8 * DIM]; x3 = xp[8 * DIM + 4]; }
            float* ah = afh + pos * 5;
            float* al = afl + pos * 5;
            const float h0 = tf32f(x0), h1 = tf32f(x1), h2 = tf32f(x2), h3 = tf32f(x3);
            ah[0] = h0; ah[1] = h1; ah[2] = h2; ah[3] = h3;
            al[0] = x0 - h0; al[1] = x1 - h1; al[2] = x2 - h2; al[3] = x3 - h3;
        }
        if (t < NTOK) ids[t] = ids_keep[w * NTOK + t];
    }
    __syncthreads();

    // ---- P1: QKV via tf32 mma + A-residual compensation. Warp owns 48 cols ----
    {
        float C[6][2][4];
        #pragma unroll
        for (int nt = 0; nt < 6; nt++) {
            const int j0 = (wid * 6 + nt) * 8 + qd * 2;
            const float2 bb = *(const float2*)(qkv_b + j0);
            #pragma unroll
            for (int mt = 0; mt < 2; mt++) {
                C[nt][mt][0] = bb.x; C[nt][mt][1] = bb.y;
                C[nt][mt][2] = bb.x; C[nt][mt][3] = bb.y;
            }
        }
        #pragma unroll
        for (int ks2 = 0; ks2 < 8; ks2++) {
            uint32_t Ah[2][2][4], Al[2][2][4];
            #pragma unroll
            for (int mt = 0; mt < 2; mt++)
                #pragma unroll
                for (int kk = 0; kk < 2; kk++) {
                    const int pos = ((mt * 16) + (ks2 * 2 + kk)) * 32 + lane;
                    const float* ah = afh + pos * 5;
                    const float* al = afl + pos * 5;
                    #pragma unroll
                    for (int e = 0; e < 4; e++) {
                        Ah[mt][kk][e] = __float_as_uint(ah[e]);
                        Al[mt][kk][e] = __float_as_uint(al[e]);
                    }
                }
            #pragma unroll
            for (int nt = 0; nt < 6; nt++) {
                const float4 bv = g_bqkv[((wid * 6 + nt) * 8 + ks2) * 32 + lane];
                const uint32_t b0 = __float_as_uint(bv.x), b1 = __float_as_uint(bv.y);
                const uint32_t b2 = __float_as_uint(bv.z), b3 = __float_as_uint(bv.w);
                MMA_TF32(C[nt][0], Ah[0][0][0], Ah[0][0][1], Ah[0][0][2], Ah[0][0][3], b0, b1);
                MMA_TF32(C[nt][0], Al[0][0][0], Al[0][0][1], Al[0][0][2], Al[0][0][3], b0, b1);
                MMA_TF32(C[nt][1], Ah[1][0][0], Ah[1][0][1], Ah[1][0][2], Ah[1][0][3], b0, b1);
                MMA_TF32(C[nt][1], Al[1][0][0], Al[1][0][1], Al[1][0][2], Al[1][0][3], b0, b1);
                MMA_TF32(C[nt][0], Ah[0][1][0], Ah[0][1][1], Ah[0][1][2], Ah[0][1][3], b2, b3);
                MMA_TF32(C[nt][0], Al[0][1][0], Al[0][1][1], Al[0][1][2], Al[0][1][3], b2, b3);
                MMA_TF32(C[nt][1], Ah[1][1][0], Ah[1][1][1], Ah[1][1][2], Ah[1][1][3], b2, b3);
                MMA_TF32(C[nt][1], Al[1][1][0], Al[1][1][1], Al[1][1][2], Al[1][1][3], b2, b3);
            }
        }
        const float scaleq = 0.17677669529663687f;
        #pragma unroll
        for (int nt = 0; nt < 6; nt++) {
            const int j0 = (wid * 6 + nt) * 8 + qd * 2;
            const int part = j0 >> 7, h = (j0 >> 5) & 3, d = j0 & 31;
            float* base = sm + OFF_QKV + part * 3600 + h * 900 + d;
            const float sc = (part == 0) ? scaleq : 1.f;
            #pragma unroll
            for (int mt = 0; mt < 2; mt++) {
                const int row = mt * 16 + g;
                *(float2*)(base + row * 36) =
                    make_float2(C[nt][mt][0] * sc, C[nt][mt][1] * sc);
                if (row + 8 < NTOK)
                    *(float2*)(base + (row + 8) * 36) =
                        make_float2(C[nt][mt][2] * sc, C[nt][mt][3] * sc);
            }
        }
    }
    __syncthreads();

    // ---- P2: attention (warps 0-3; warp=head, lane=token). Output -> af hi/lo ----
    if (t < 128) {
        const int h = wid, n = lane;
        if (n < NTOK) {
            float r[NTOK];
            const int in_ = ids[n];
            const float* mrow = mask + w * (WSQ * WSQ) + in_ * WSQ;
            const int* rrow = rel_index + in_ * WSQ;
            #pragma unroll
            for (int m = 0; m < NTOK; m++) {
                const int im = ids[m];
                r[m] = bias_table[rrow[im] * NH + h] + mrow[im];
            }
            {   // scores: full 32-dim q dot k
                ulonglong2 q8[8];
                const ulonglong2* qr = (const ulonglong2*)(sm + OFF_QKV + h * 900 + n * 36);
                #pragma unroll
                for (int p = 0; p < 8; p++) q8[p] = qr[p];
                #pragma unroll
                for (int m = 0; m < NTOK; m++) {
                    const ulonglong2* kr = (const ulonglong2*)(sm + OFF_QKV + 3600 + h * 900 + m * 36);
                    u64t a0 = 0, a1 = 0, a2 = 0, a3 = 0;
                    #pragma unroll
                    for (int p = 0; p < 8; p += 2) {
                        const ulonglong2 kv0 = kr[p];
                        FMA2(a0, q8[p].x, kv0.x, a0);
                        FMA2(a1, q8[p].y, kv0.y, a1);
                        const ulonglong2 kv1 = kr[p + 1];
                        FMA2(a2, q8[p + 1].x, kv1.x, a2);
                        FMA2(a3, q8[p + 1].y, kv1.y, a3);
                    }
                    ADD2(a0, a0, a2);
                    ADD2(a1, a1, a3);
                    ADD2(a0, a0, a1);
                    const float2 u = unpack2(a0);
                    r[m] += u.x + u.y;
                }
            }
            // softmax in registers
            float mx = r[0];
            #pragma unroll
            for (int m = 1; m < NTOK; m++) mx = fmaxf(mx, r[m]);
            float s = 0.f;
            #pragma unroll
            for (int m = 0; m < NTOK; m++) { r[m] = __expf(r[m] - mx); s += r[m]; }
            const float inv = 1.0f / s;
            #pragma unroll
            for (int m = 0; m < NTOK; m++) r[m] *= inv;
            // AV in two 16-wide halves; store hi/lo A-frag layout
            const int rr = n & 15;
            const int g2 = rr & 7;
            const int rowbit = rr >> 3;
            const int mtb = (n >> 4) * 16;
            #pragma unroll
            for (int half = 0; half < 2; half++) {
                u64t o2[8];
                #pragma unroll
                for (int p = 0; p < 8; p++) o2[p] = 0;
                #pragma unroll
                for (int m = 0; m < NTOK; m++) {
                    const ulonglong2* vr =
                        (const ulonglong2*)(sm + OFF_QKV + 7200 + h * 900 + m * 36 + half * 16);
                    const u64t pm = pack2(r[m], r[m]);
                    #pragma unroll
                    for (int p = 0; p < 4; p++) {
                        const ulonglong2 vv = vr[p];
                        FMA2(o2[2 * p],     vv.x, pm, o2[2 * p]);
                        FMA2(o2[2 * p + 1], vv.y, pm, o2[2 * p + 1]);
                    }
                }
                #pragma unroll
                for (int p = 0; p < 8; p++) {
                    const float2 u = unpack2(o2[p]);
                    const int c0 = h * 32 + half * 16 + 2 * p;
                    {
                        const int adr = ((mtb + (c0 >> 3)) * 32 + g2 * 4 + (c0 & 3)) * 5
                                        + ((c0 & 4) ? 2 : 0) + rowbit;
                        const float hv = tf32f(u.x);
                        afh[adr] = hv; afl[adr] = u.x - hv;
                    }
                    {
                        const int c1 = c0 + 1;
                        const int adr = ((mtb + (c1 >> 3)) * 32 + g2 * 4 + (c1 & 3)) * 5
                                        + ((c1 & 4) ? 2 : 0) + rowbit;
                        const float hv = tf32f(u.y);
                        afh[adr] = hv; afl[adr] = u.y - hv;
                    }
                }
            }
        }
    }
    __syncthreads();

    // ---- P3: proj via tf32 mma + A-residual. Warp owns 16 cols ----
    {
        float C[2][2][4];
        #pragma unroll
        for (int nt2 = 0; nt2 < 2; nt2++) {
            const int j0 = (wid * 2 + nt2) * 8 + qd * 2;
            const float2 bb = *(const float2*)(proj_b + j0);
            #pragma unroll
            for (int mt = 0; mt < 2; mt++) {
                C[nt2][mt][0] = bb.x; C[nt2][mt][1] = bb.y;
                C[nt2][mt][2] = bb.x; C[nt2][mt][3] = bb.y;
            }
        }
        #pragma unroll
        for (int ks2 = 0; ks2 < 8; ks2++) {
            uint32_t Ah[2][2][4], Al[2][2][4];
            #pragma unroll
            for (int mt = 0; mt < 2; mt++)
                #pragma unroll
                for (int kk = 0; kk < 2; kk++) {
                    const int pos = ((mt * 16) + (ks2 * 2 + kk)) * 32 + lane;
                    const float* ah = afh + pos * 5;
                    const float* al = afl + pos * 5;
                    #pragma unroll
                    for (int e = 0; e < 4; e++) {
                        Ah[mt][kk][e] = __float_as_uint(ah[e]);
                        Al[mt][kk][e] = __float_as_uint(al[e]);
                    }
                }
            #pragma unroll
            for (int nt2 = 0; nt2 < 2; nt2++) {
                const float4 bv = g_bproj[((wid * 2 + nt2) * 8 + ks2) * 32 + lane];
                const uint32_t b0 = __float_as_uint(bv.x), b1 = __float_as_uint(bv.y);
                const uint32_t b2 = __float_as_uint(bv.z), b3 = __float_as_uint(bv.w);
                MMA_TF32(C[nt2][0], Ah[0][0][0], Ah[0][0][1], Ah[0][0][2], Ah[0][0][3], b0, b1);
                MMA_TF32(C[nt2][0], Al[0][0][0], Al[0][0][1], Al[0][0][2], Al[0][0][3], b0, b1);
                MMA_TF32(C[nt2][1], Ah[1][0][0], Ah[1][0][1], Ah[1][0][2], Ah[1][0][3], b0, b1);
                MMA_TF32(C[nt2][1], Al[1][0][0], Al[1][0][1], Al[1][0][2], Al[1][0][3], b0, b1);
                MMA_TF32(C[nt2][0], Ah[0][1][0], Ah[0][1][1], Ah[0][1][2], Ah[0][1][3], b2, b3);
                MMA_TF32(C[nt2][0], Al[0][1][0], Al[0][1][1], Al[0][1][2], Al[0][1][3], b2, b3);
                MMA_TF32(C[nt2][1], Ah[1][1][0], Ah[1][1][1], Ah[1][1][2], Ah[1][1][3], b2, b3);
                MMA_TF32(C[nt2][1], Al[1][1][0], Al[1][1][1], Al[1][1][2], Al[1][1][3], b2, b3);
            }
        }
        float* ob = out + (size_t)b * (NTOK * DIM);
        #pragma unroll
        for (int nt2 = 0; nt2 < 2; nt2++) {
            const int j0 = (wid * 2 + nt2) * 8 + qd * 2;
            #pragma unroll
            for (int mt = 0; mt < 2; mt++) {
                const int row = mt * 16 + g;
                if (row < NTOK)
                    *(float2*)(ob + row * DIM + j0) = make_float2(C[nt2][mt][0], C[nt2][mt][1]);
                if (row + 8 < NTOK)
                    *(float2*)(ob + (row + 8) * DIM + j0) = make_float2(C[nt2][mt][2], C[nt2][mt][3]);
            }
        }
    }
}

extern "C" void kernel_launch(void* const* d_in, const int* in_sizes, int n_in,
                              void* d_out, int out_size)
{
    const float* x          = (const float*)d_in[0];
    const float* mask       = (const float*)d_in[1];
    const int*   ids_keep   = (const int*)  d_in[2];
    const float* qkv_w      = (const float*)d_in[3];
    const float* qkv_b      = (const float*)d_in[4];
    const float* proj_w     = (const float*)d_in[5];
    const float* proj_b     = (const float*)d_in[6];
    const float* bias_table = (const float*)d_in[7];
    const int*   rel_index  = (const int*)  d_in[8];

    pack_weights<<<64, 256>>>(qkv_w, proj_w);

    const int smem_bytes = SM_FLOATS * 4;
    cudaFuncSetAttribute(win_attn_kernel,
                         cudaFuncAttributeMaxDynamicSharedMemorySize, smem_bytes);
    win_attn_kernel<<<4096, 256, smem_bytes>>>(
        x, mask, ids_keep, qkv_b, proj_b, bias_table, rel_index, (float*)d_out);
}

// round 6
// speedup vs baseline: 2.6517x; 1.2127x over previous
#include <cuda_runtime.h>
#include <cstdint>

#define NTOK 25
#define DIM  128
#define NH   4
#define NWIN 64
#define WSQ  49

typedef unsigned long long u64t;

// Weight fragments, tf32-converted, B-frag order (float4 = 2 k-steps).
__device__ float4 g_bqkv[48 * 8 * 32];   // [nt(48)][ks2(8)][lane(32)]
__device__ float4 g_bproj[16 * 8 * 32];  // [nt(16)][ks2(8)][lane(32)]

__device__ __forceinline__ uint32_t to_tf32(float f) {
    uint32_t u; asm("cvt.rna.tf32.f32 %0, %1;" : "=r"(u) : "f"(f)); return u;
}
__device__ __forceinline__ float tf32f(float f) { return __uint_as_float(to_tf32(f)); }

__global__ void pack_weights(const float* __restrict__ qkv_w,
                             const float* __restrict__ proj_w)
{
    const int p = blockIdx.x * 256 + threadIdx.x;     // 64 x 256 = 16384
    const int l = p & 31;
    const int ks2 = (p >> 5) & 7;
    if (p < 48 * 8 * 32) {
        const int nt = p >> 8;
        const int n = nt * 8 + (l >> 2);
        const int k = ks2 * 16 + (l & 3);
        const float* wr = qkv_w + n * DIM + k;
        g_bqkv[p] = make_float4(tf32f(wr[0]), tf32f(wr[4]), tf32f(wr[8]), tf32f(wr[12]));
    } else {
        const int q = p - 48 * 8 * 32;
        const int nt = q >> 8;
        const int n = nt * 8 + (l >> 2);
        const int k = ks2 * 16 + (l & 3);
        const float* wr = proj_w + n * DIM + k;
        g_bproj[q] = make_float4(tf32f(wr[0]), tf32f(wr[4]), tf32f(wr[8]), tf32f(wr[12]));
    }
}

#define MMA_TF32(Cv, a0, a1, a2, a3, b0, b1)                          \
    asm("mma.sync.aligned.m16n8k8.row.col.f32.tf32.tf32.f32 "          \
        "{%0,%1,%2,%3}, {%4,%5,%6,%7}, {%8,%9}, {%0,%1,%2,%3};"        \
        : "+f"(Cv[0]), "+f"(Cv[1]), "+f"(Cv[2]), "+f"(Cv[3])           \
        : "r"(a0), "r"(a1), "r"(a2), "r"(a3), "r"(b0), "r"(b1))

__device__ __forceinline__ u64t pack2(float lo, float hi) {
    u64t r; asm("mov.b64 %0, {%1, %2};" : "=l"(r) : "f"(lo), "f"(hi)); return r;
}
__device__ __forceinline__ float2 unpack2(u64t v) {
    float2 r; asm("mov.b64 {%0, %1}, %2;" : "=f"(r.x), "=f"(r.y) : "l"(v)); return r;
}
#define FMA2(d, a, b, c) \
    asm("fma.rn.f32x2 %0, %1, %2, %3;" : "=l"(d) : "l"(a), "l"(b), "l"(c))
#define ADD2(d, a, b) \
    asm("add.rn.f32x2 %0, %1, %2;" : "=l"(d) : "l"(a), "l"(b))

// Shared layout (floats):
//   af   [0, 4096)          A-frags tf32 (1024 pos x 4, float4 aligned, conflict-free)
//   qs/ks/vs [4096, 14896)  [part][h][tok][36]
//   ids at 14896
#define OFF_QKV 4096
#define OFF_IDS 14896
#define SM_FLOATS 14928

__global__ __launch_bounds__(256, 2)
void win_attn_kernel(const float* __restrict__ x,
                     const float* __restrict__ mask,
                     const int*   __restrict__ ids_keep,
                     const float* __restrict__ qkv_b,
                     const float* __restrict__ proj_b,
                     const float* __restrict__ bias_table,
                     const int*   __restrict__ rel_index,
                     float* __restrict__ out)
{
    extern __shared__ float sm[];
    float* af = sm;
    int* ids = (int*)(sm + OFF_IDS);

    const int b = blockIdx.x;
    const int w = b & (NWIN - 1);
    const int t = threadIdx.x;
    const int wid = t >> 5, lane = t & 31;
    const int g = lane >> 2, qd = lane & 3;

    // ---- P0: pack x into A-frag layout (tf32), rows >= 25 zeroed ----
    {
        const float* xb = x + (size_t)b * (NTOK * DIM);
        #pragma unroll
        for (int i = 0; i < 4; i++) {
            const int pos = t + 256 * i;
            const int l = pos & 31, ksv = (pos >> 5) & 15, mt = pos >> 9;
            const int r0 = mt * 16 + (l >> 2);
            const int c0 = ksv * 8 + (l & 3);
            const float* xp = xb + r0 * DIM + c0;
            const float x0 = xp[0], x2 = xp[4];
            float x1 = 0.f, x3 = 0.f;
            if (r0 + 8 < NTOK) { x1 = xp[8 * DIM]; x3 = xp[8 * DIM + 4]; }
            *(float4*)(af + pos * 4) =
                make_float4(tf32f(x0), tf32f(x1), tf32f(x2), tf32f(x3));
        }
        if (t < NTOK) ids[t] = ids_keep[w * NTOK + t];
    }
    __syncthreads();

    // ---- P1: QKV via tf32 mma. Warp owns 48 cols (6 ntiles) ----
    {
        float C[6][2][4];
        #pragma unroll
        for (int nt = 0; nt < 6; nt++) {
            const int j0 = (wid * 6 + nt) * 8 + qd * 2;
            const float2 bb = *(const float2*)(qkv_b + j0);
            #pragma unroll
            for (int mt = 0; mt < 2; mt++) {
                C[nt][mt][0] = bb.x; C[nt][mt][1] = bb.y;
                C[nt][mt][2] = bb.x; C[nt][mt][3] = bb.y;
            }
        }
        #pragma unroll
        for (int ks2 = 0; ks2 < 8; ks2++) {
            uint32_t A[2][2][4];
            #pragma unroll
            for (int mt = 0; mt < 2; mt++)
                #pragma unroll
                for (int kk = 0; kk < 2; kk++) {
                    const int pos = ((mt * 16) + (ks2 * 2 + kk)) * 32 + lane;
                    const float4 av = *(const float4*)(af + pos * 4);
                    A[mt][kk][0] = __float_as_uint(av.x);
                    A[mt][kk][1] = __float_as_uint(av.y);
                    A[mt][kk][2] = __float_as_uint(av.z);
                    A[mt][kk][3] = __float_as_uint(av.w);
                }
            #pragma unroll
            for (int nt = 0; nt < 6; nt++) {
                const float4 bv = g_bqkv[((wid * 6 + nt) * 8 + ks2) * 32 + lane];
                const uint32_t b0 = __float_as_uint(bv.x), b1 = __float_as_uint(bv.y);
                const uint32_t b2 = __float_as_uint(bv.z), b3 = __float_as_uint(bv.w);
                MMA_TF32(C[nt][0], A[0][0][0], A[0][0][1], A[0][0][2], A[0][0][3], b0, b1);
                MMA_TF32(C[nt][1], A[1][0][0], A[1][0][1], A[1][0][2], A[1][0][3], b0, b1);
                MMA_TF32(C[nt][0], A[0][1][0], A[0][1][1], A[0][1][2], A[0][1][3], b2, b3);
                MMA_TF32(C[nt][1], A[1][1][0], A[1][1][1], A[1][1][2], A[1][1][3], b2, b3);
            }
        }
        const float scaleq = 0.17677669529663687f;
        #pragma unroll
        for (int nt = 0; nt < 6; nt++) {
            const int j0 = (wid * 6 + nt) * 8 + qd * 2;
            const int part = j0 >> 7, h = (j0 >> 5) & 3, d = j0 & 31;
            float* base = sm + OFF_QKV + part * 3600 + h * 900 + d;
            const float sc = (part == 0) ? scaleq : 1.f;
            #pragma unroll
            for (int mt = 0; mt < 2; mt++) {
                const int row = mt * 16 + g;
                *(float2*)(base + row * 36) =
                    make_float2(C[nt][mt][0] * sc, C[nt][mt][1] * sc);
                if (row + 8 < NTOK)
                    *(float2*)(base + (row + 8) * 36) =
                        make_float2(C[nt][mt][2] * sc, C[nt][mt][3] * sc);
            }
        }
    }
    __syncthreads();

    // ---- P2: attention (warps 0-3; warp=head, lane=token). Output -> af (tf32) ----
    if (t < 128) {
        const int h = wid, n = lane;
        if (n < NTOK) {
            float r[NTOK];
            const int in_ = ids[n];
            const float* mrow = mask + w * (WSQ * WSQ) + in_ * WSQ;
            const int* rrow = rel_index + in_ * WSQ;
            #pragma unroll
            for (int m = 0; m < NTOK; m++) {
                const int im = ids[m];
                r[m] = bias_table[rrow[im] * NH + h] + mrow[im];
            }
            {   // scores: full 32-dim q dot k
                ulonglong2 q8[8];
                const ulonglong2* qr = (const ulonglong2*)(sm + OFF_QKV + h * 900 + n * 36);
                #pragma unroll
                for (int p = 0; p < 8; p++) q8[p] = qr[p];
                #pragma unroll
                for (int m = 0; m < NTOK; m++) {
                    const ulonglong2* kr = (const ulonglong2*)(sm + OFF_QKV + 3600 + h * 900 + m * 36);
                    u64t a0 = 0, a1 = 0, a2 = 0, a3 = 0;
                    #pragma unroll
                    for (int p = 0; p < 8; p += 2) {
                        const ulonglong2 kv0 = kr[p];
                        FMA2(a0, q8[p].x, kv0.x, a0);
                        FMA2(a1, q8[p].y, kv0.y, a1);
                        const ulonglong2 kv1 = kr[p + 1];
                        FMA2(a2, q8[p + 1].x, kv1.x, a2);
                        FMA2(a3, q8[p + 1].y, kv1.y, a3);
                    }
                    ADD2(a0, a0, a2);
                    ADD2(a1, a1, a3);
                    ADD2(a0, a0, a1);
                    const float2 u = unpack2(a0);
                    r[m] += u.x + u.y;
                }
            }
            // softmax in registers
            float mx = r[0];
            #pragma unroll
            for (int m = 1; m < NTOK; m++) mx = fmaxf(mx, r[m]);
            float s = 0.f;
            #pragma unroll
            for (int m = 0; m < NTOK; m++) { r[m] = __expf(r[m] - mx); s += r[m]; }
            const float inv = 1.0f / s;
            #pragma unroll
            for (int m = 0; m < NTOK; m++) r[m] *= inv;
            // AV in two 16-wide halves; store tf32 A-frag layout (stride 4)
            const int rr = n & 15;
            const int g2 = rr & 7;
            const int rowbit = rr >> 3;
            const int mtb = (n >> 4) * 16;
            #pragma unroll
            for (int half = 0; half < 2; half++) {
                u64t o2[8];
                #pragma unroll
                for (int p = 0; p < 8; p++) o2[p] = 0;
                #pragma unroll
                for (int m = 0; m < NTOK; m++) {
                    const ulonglong2* vr =
                        (const ulonglong2*)(sm + OFF_QKV + 7200 + h * 900 + m * 36 + half * 16);
                    const u64t pm = pack2(r[m], r[m]);
                    #pragma unroll
                    for (int p = 0; p < 4; p++) {
                        const ulonglong2 vv = vr[p];
                        FMA2(o2[2 * p],     vv.x, pm, o2[2 * p]);
                        FMA2(o2[2 * p + 1], vv.y, pm, o2[2 * p + 1]);
                    }
                }
                #pragma unroll
                for (int p = 0; p < 8; p++) {
                    const float2 u = unpack2(o2[p]);
                    const int c0 = h * 32 + half * 16 + 2 * p;
                    {
                        const int adr = ((mtb + (c0 >> 3)) * 32 + g2 * 4 + (c0 & 3)) * 4
                                        + ((c0 & 4) ? 2 : 0) + rowbit;
                        af[adr] = tf32f(u.x);
                    }
                    {
                        const int c1 = c0 + 1;
                        const int adr = ((mtb + (c1 >> 3)) * 32 + g2 * 4 + (c1 & 3)) * 4
                                        + ((c1 & 4) ? 2 : 0) + rowbit;
                        af[adr] = tf32f(u.y);
                    }
                }
            }
        }
    }
    __syncthreads();

    // ---- P3: proj via tf32 mma. Warp owns 16 cols (2 ntiles) ----
    {
        float C[2][2][4];
        #pragma unroll
        for (int nt2 = 0; nt2 < 2; nt2++) {
            const int j0 = (wid * 2 + nt2) * 8 + qd * 2;
            const float2 bb = *(const float2*)(proj_b + j0);
            #pragma unroll
            for (int mt = 0; mt < 2; mt++) {
                C[nt2][mt][0] = bb.x; C[nt2][mt][1] = bb.y;
                C[nt2][mt][2] = bb.x; C[nt2][mt][3] = bb.y;
            }
        }
        #pragma unroll
        for (int ks2 = 0; ks2 < 8; ks2++) {
            uint32_t A[2][2][4];
            #pragma unroll
            for (int mt = 0; mt < 2; mt++)
                #pragma unroll
                for (int kk = 0; kk < 2; kk++) {
                    const int pos = ((mt * 16) + (ks2 * 2 + kk)) * 32 + lane;
                    const float4 av = *(const float4*)(af + pos * 4);
                    A[mt][kk][0] = __float_as_uint(av.x);
                    A[mt][kk][1] = __float_as_uint(av.y);
                    A[mt][kk][2] = __float_as_uint(av.z);
                    A[mt][kk][3] = __float_as_uint(av.w);
                }
            #pragma unroll
            for (int nt2 = 0; nt2 < 2; nt2++) {
                const float4 bv = g_bproj[((wid * 2 + nt2) * 8 + ks2) * 32 + lane];
                const uint32_t b0 = __float_as_uint(bv.x), b1 = __float_as_uint(bv.y);
                const uint32_t b2 = __float_as_uint(bv.z), b3 = __float_as_uint(bv.w);
                MMA_TF32(C[nt2][0], A[0][0][0], A[0][0][1], A[0][0][2], A[0][0][3], b0, b1);
                MMA_TF32(C[nt2][1], A[1][0][0], A[1][0][1], A[1][0][2], A[1][0][3], b0, b1);
                MMA_TF32(C[nt2][0], A[0][1][0], A[0][1][1], A[0][1][2], A[0][1][3], b2, b3);
                MMA_TF32(C[nt2][1], A[1][1][0], A[1][1][1], A[1][1][2], A[1][1][3], b2, b3);
            }
        }
        float* ob = out + (size_t)b * (NTOK * DIM);
        #pragma unroll
        for (int nt2 = 0; nt2 < 2; nt2++) {
            const int j0 = (wid * 2 + nt2) * 8 + qd * 2;
            #pragma unroll
            for (int mt = 0; mt < 2; mt++) {
                const int row = mt * 16 + g;
                if (row < NTOK)
                    *(float2*)(ob + row * DIM + j0) = make_float2(C[nt2][mt][0], C[nt2][mt][1]);
                if (row + 8 < NTOK)
                    *(float2*)(ob + (row + 8) * DIM + j0) = make_float2(C[nt2][mt][2], C[nt2][mt][3]);
            }
        }
    }
}

extern "C" void kernel_launch(void* const* d_in, const int* in_sizes, int n_in,
                              void* d_out, int out_size)
{
    const float* x          = (const float*)d_in[0];
    const float* mask       = (const float*)d_in[1];
    const int*   ids_keep   = (const int*)  d_in[2];
    const float* qkv_w      = (const float*)d_in[3];
    const float* qkv_b      = (const float*)d_in[4];
    const float* proj_w     = (const float*)d_in[5];
    const float* proj_b     = (const float*)d_in[6];
    const float* bias_table = (const float*)d_in[7];
    const int*   rel_index  = (const int*)  d_in[8];

    pack_weights<<<64, 256>>>(qkv_w, proj_w);

    const int smem_bytes = SM_FLOATS * 4;
    cudaFuncSetAttribute(win_attn_kernel,
                         cudaFuncAttributeMaxDynamicSharedMemorySize, smem_bytes);
    win_attn_kernel<<<4096, 256, smem_bytes>>>(
        x, mask, ids_keep, qkv_b, proj_b, bias_table, rel_index, (float*)d_out);
}

// round 7
// speedup vs baseline: 2.9270x; 1.1038x over previous
#include <cuda_runtime.h>
#include <cstdint>

#define NTOK 25
#define DIM  128
#define NH   4
#define NWIN 64
#define WSQ  49

typedef unsigned long long u64t;

// Weight fragments, tf32-converted, B-frag order (float4 = 2 k-steps).
__device__ float4 g_bqkv[48 * 8 * 32];   // [nt(48)][ks2(8)][lane(32)]
__device__ float4 g_bproj[16 * 8 * 32];  // [nt(16)][ks2(8)][lane(32)]
// Precomputed bias+mask: [w][h][m][n]  (n innermost for coalesced lane reads)
__device__ float g_bm[NWIN * NH * NTOK * NTOK];

__device__ __forceinline__ uint32_t to_tf32(float f) {
    uint32_t u; asm("cvt.rna.tf32.f32 %0, %1;" : "=r"(u) : "f"(f)); return u;
}
__device__ __forceinline__ float tf32f(float f) { return __uint_as_float(to_tf32(f)); }

__global__ void pack_weights(const float* __restrict__ qkv_w,
                             const float* __restrict__ proj_w)
{
    const int p = blockIdx.x * 256 + threadIdx.x;     // 64 x 256 = 16384
    const int l = p & 31;
    const int ks2 = (p >> 5) & 7;
    if (p < 48 * 8 * 32) {
        const int nt = p >> 8;
        const int n = nt * 8 + (l >> 2);
        const int k = ks2 * 16 + (l & 3);
        const float* wr = qkv_w + n * DIM + k;
        g_bqkv[p] = make_float4(tf32f(wr[0]), tf32f(wr[4]), tf32f(wr[8]), tf32f(wr[12]));
    } else {
        const int q = p - 48 * 8 * 32;
        const int nt = q >> 8;
        const int n = nt * 8 + (l >> 2);
        const int k = ks2 * 16 + (l & 3);
        const float* wr = proj_w + n * DIM + k;
        g_bproj[q] = make_float4(tf32f(wr[0]), tf32f(wr[4]), tf32f(wr[8]), tf32f(wr[12]));
    }
}

__global__ void fill_bm(const float* __restrict__ mask,
                        const int*   __restrict__ ids_keep,
                        const float* __restrict__ bias_table,
                        const int*   __restrict__ rel_index)
{
    const int idx = blockIdx.x * 256 + threadIdx.x;   // 625 x 256 >= 160000
    if (idx >= NWIN * NH * NTOK * NTOK) return;
    const int w = idx / (NH * NTOK * NTOK);
    const int rem = idx - w * (NH * NTOK * NTOK);
    const int h = rem / (NTOK * NTOK);
    const int r2 = rem - h * (NTOK * NTOK);
    const int m = r2 / NTOK, n = r2 - m * NTOK;
    const int in_ = ids_keep[w * NTOK + n];
    const int im  = ids_keep[w * NTOK + m];
    g_bm[idx] = bias_table[rel_index[in_ * WSQ + im] * NH + h]
              + mask[(w * WSQ + in_) * WSQ + im];
}

#define MMA_TF32(Cv, a0, a1, a2, a3, b0, b1)                          \
    asm("mma.sync.aligned.m16n8k8.row.col.f32.tf32.tf32.f32 "          \
        "{%0,%1,%2,%3}, {%4,%5,%6,%7}, {%8,%9}, {%0,%1,%2,%3};"        \
        : "+f"(Cv[0]), "+f"(Cv[1]), "+f"(Cv[2]), "+f"(Cv[3])           \
        : "r"(a0), "r"(a1), "r"(a2), "r"(a3), "r"(b0), "r"(b1))

__device__ __forceinline__ u64t pack2(float lo, float hi) {
    u64t r; asm("mov.b64 %0, {%1, %2};" : "=l"(r) : "f"(lo), "f"(hi)); return r;
}
__device__ __forceinline__ float2 unpack2(u64t v) {
    float2 r; asm("mov.b64 {%0, %1}, %2;" : "=f"(r.x), "=f"(r.y) : "l"(v)); return r;
}
#define FMA2(d, a, b, c) \
    asm("fma.rn.f32x2 %0, %1, %2, %3;" : "=l"(d) : "l"(a), "l"(b), "l"(c))
#define ADD2(d, a, b) \
    asm("add.rn.f32x2 %0, %1, %2;" : "=l"(d) : "l"(a), "l"(b))

// A-frag address with chunk-XOR swizzle (float index). chunk,l_mma in [0,32), e in [0,4).
__device__ __forceinline__ int af_addr(int chunk, int l_mma, int e) {
    return ((chunk ^ ((l_mma >> 2) & 7)) * 32 + l_mma) * 4 + e;
}

// Shared layout (floats):
//   af   [0, 4096)           A-frags tf32 (chunk-XOR swizzled)
//   qs   [4096, 9216)        q swizzled: [h][row32][40], chunk-XOR by row
//   ks   [9216, 12816)       [h][tok][36]
//   vs   [12816, 16416)      [h][tok][36]  (also P0 staging: 25 x 136 = 3400)
#define OFF_Q  4096
#define OFF_K  9216
#define OFF_V  12816
#define SM_FLOATS 16448

__global__ __launch_bounds__(256, 2)
void win_attn_kernel(const float* __restrict__ x,
                     const float* __restrict__ qkv_b,
                     const float* __restrict__ proj_b,
                     float* __restrict__ out)
{
    extern __shared__ float sm[];
    float* af = sm;
    float* qs = sm + OFF_Q;
    float* ks = sm + OFF_K;
    float* vs = sm + OFF_V;
    float* xstg = vs;            // P0 staging, consumed before P1 writes vs

    const int b = blockIdx.x;
    const int w = b & (NWIN - 1);
    const int t = threadIdx.x;
    const int wid = t >> 5, lane = t & 31;
    const int g = lane >> 2, qd = lane & 3;

    // ---- P0a: coalesced load x -> linear staging [row][136] ----
    {
        const float4* xb4 = (const float4*)(x + (size_t)b * (NTOK * DIM));
        #pragma unroll
        for (int i = 0; i < 3; i++) {
            const int e4 = t + 256 * i;                 // float4 index, row-uniform per warp
            const int row = e4 >> 5, col4 = e4 & 31;
            *(float4*)(xstg + row * 136 + col4 * 4) = xb4[e4];
        }
        if (t < 32) {
            const int e4 = 768 + t;
            const int row = e4 >> 5, col4 = e4 & 31;
            *(float4*)(xstg + row * 136 + col4 * 4) = xb4[e4];
        }
    }
    __syncthreads();

    // ---- P0b: pack staging -> A-frag layout (tf32, swizzled), rows >= 25 zeroed ----
    #pragma unroll
    for (int i = 0; i < 4; i++) {
        const int pos = t + 256 * i;
        const int l = pos & 31, chunk = pos >> 5;
        const int ksv = chunk & 15, mt = chunk >> 4;
        const int r0 = mt * 16 + (l >> 2);
        const int c0 = ksv * 8 + (l & 3);
        const float* sp = xstg + r0 * 136 + c0;
        const float x0 = sp[0], x2 = sp[4];
        float x1 = 0.f, x3 = 0.f;
        if (r0 + 8 < NTOK) { x1 = sp[8 * 136]; x3 = sp[8 * 136 + 4]; }
        *(float4*)(af + af_addr(chunk, l, 0)) =
            make_float4(tf32f(x0), tf32f(x1), tf32f(x2), tf32f(x3));
    }
    __syncthreads();

    // ---- P1: QKV via tf32 mma. Warp owns 48 cols (6 ntiles) ----
    {
        float C[6][2][4];
        #pragma unroll
        for (int nt = 0; nt < 6; nt++) {
            const int j0 = (wid * 6 + nt) * 8 + qd * 2;
            const float2 bb = *(const float2*)(qkv_b + j0);
            #pragma unroll
            for (int mt = 0; mt < 2; mt++) {
                C[nt][mt][0] = bb.x; C[nt][mt][1] = bb.y;
                C[nt][mt][2] = bb.x; C[nt][mt][3] = bb.y;
            }
        }
        #pragma unroll
        for (int ks2 = 0; ks2 < 8; ks2++) {
            uint32_t A[2][2][4];
            #pragma unroll
            for (int mt = 0; mt < 2; mt++)
                #pragma unroll
                for (int kk = 0; kk < 2; kk++) {
                    const float4 av = *(const float4*)(af + af_addr(mt * 16 + ks2 * 2 + kk, lane, 0));
                    A[mt][kk][0] = __float_as_uint(av.x);
                    A[mt][kk][1] = __float_as_uint(av.y);
                    A[mt][kk][2] = __float_as_uint(av.z);
                    A[mt][kk][3] = __float_as_uint(av.w);
                }
            #pragma unroll
            for (int nt = 0; nt < 6; nt++) {
                const float4 bv = g_bqkv[((wid * 6 + nt) * 8 + ks2) * 32 + lane];
                const uint32_t b0 = __float_as_uint(bv.x), b1 = __float_as_uint(bv.y);
                const uint32_t b2 = __float_as_uint(bv.z), b3 = __float_as_uint(bv.w);
                MMA_TF32(C[nt][0], A[0][0][0], A[0][0][1], A[0][0][2], A[0][0][3], b0, b1);
                MMA_TF32(C[nt][1], A[1][0][0], A[1][0][1], A[1][0][2], A[1][0][3], b0, b1);
                MMA_TF32(C[nt][0], A[0][1][0], A[0][1][1], A[0][1][2], A[0][1][3], b2, b3);
                MMA_TF32(C[nt][1], A[1][1][0], A[1][1][1], A[1][1][2], A[1][1][3], b2, b3);
            }
        }
        const float scaleq = 0.17677669529663687f;
        #pragma unroll
        for (int nt = 0; nt < 6; nt++) {
            const int j0 = (wid * 6 + nt) * 8 + qd * 2;
            const int part = j0 >> 7, h = (j0 >> 5) & 3, d0 = j0 & 31;
            if (part == 0) {
                #pragma unroll
                for (int mt = 0; mt < 2; mt++) {
                    const int row = mt * 16 + g;
                    const int phys = (d0 >> 2) ^ ((row >> 2) & 7);
                    *(float2*)(qs + h * 1280 + row * 40 + phys * 4 + (d0 & 3)) =
                        make_float2(C[nt][mt][0] * scaleq, C[nt][mt][1] * scaleq);
                    const int row2 = row + 8;
                    if (row2 < NTOK) {
                        const int phys2 = (d0 >> 2) ^ ((row2 >> 2) & 7);
                        *(float2*)(qs + h * 1280 + row2 * 40 + phys2 * 4 + (d0 & 3)) =
                            make_float2(C[nt][mt][2] * scaleq, C[nt][mt][3] * scaleq);
                    }
                }
            } else {
                float* base = (part == 1 ? ks : vs) + h * 900 + d0;
                #pragma unroll
                for (int mt = 0; mt < 2; mt++) {
                    const int row = mt * 16 + g;
                    *(float2*)(base + row * 36) = make_float2(C[nt][mt][0], C[nt][mt][1]);
                    if (row + 8 < NTOK)
                        *(float2*)(base + (row + 8) * 36) = make_float2(C[nt][mt][2], C[nt][mt][3]);
                }
            }
        }
    }
    __syncthreads();

    // ---- P2: attention (warps 0-3; warp=head, lane=token). Output -> af (tf32) ----
    if (t < 128) {
        const int h = wid, n = lane;
        if (n < NTOK) {
            float r[NTOK];
            const float* bmb = g_bm + ((w * NH + h) * NTOK) * NTOK + n;
            #pragma unroll
            for (int m = 0; m < NTOK; m++) r[m] = bmb[m * NTOK];
            {   // scores: q (swizzled regs) dot k (broadcast rows)
                ulonglong2 q8[8];
                const int swz = (n >> 2) & 7;
                const float* qb = qs + h * 1280 + n * 40;
                #pragma unroll
                for (int p = 0; p < 8; p++)
                    q8[p] = *(const ulonglong2*)(qb + (p ^ swz) * 4);
                #pragma unroll
                for (int m = 0; m < NTOK; m++) {
                    const ulonglong2* kr = (const ulonglong2*)(ks + h * 900 + m * 36);
                    u64t a0 = 0, a1 = 0, a2 = 0, a3 = 0;
                    #pragma unroll
                    for (int p = 0; p < 8; p += 2) {
                        const ulonglong2 kv0 = kr[p];
                        FMA2(a0, q8[p].x, kv0.x, a0);
                        FMA2(a1, q8[p].y, kv0.y, a1);
                        const ulonglong2 kv1 = kr[p + 1];
                        FMA2(a2, q8[p + 1].x, kv1.x, a2);
                        FMA2(a3, q8[p + 1].y, kv1.y, a3);
                    }
                    ADD2(a0, a0, a2);
                    ADD2(a1, a1, a3);
                    ADD2(a0, a0, a1);
                    const float2 u = unpack2(a0);
                    r[m] += u.x + u.y;
                }
            }
            // softmax in registers
            float mx = r[0];
            #pragma unroll
            for (int m = 1; m < NTOK; m++) mx = fmaxf(mx, r[m]);
            float s = 0.f;
            #pragma unroll
            for (int m = 0; m < NTOK; m++) { r[m] = __expf(r[m] - mx); s += r[m]; }
            const float inv = 1.0f / s;
            #pragma unroll
            for (int m = 0; m < NTOK; m++) r[m] *= inv;
            // AV in two 16-wide halves; store tf32 to swizzled A-frag layout
            const int lrow = (n & 7) * 4;
            const int chnk_row = (n >> 4) * 16;
            const int ebase = (n >> 3) & 1;
            #pragma unroll
            for (int half = 0; half < 2; half++) {
                u64t o2[8];
                #pragma unroll
                for (int p = 0; p < 8; p++) o2[p] = 0;
                #pragma unroll
                for (int m = 0; m < NTOK; m++) {
                    const ulonglong2* vr =
                        (const ulonglong2*)(vs + h * 900 + m * 36 + half * 16);
                    const u64t pm = pack2(r[m], r[m]);
                    #pragma unroll
                    for (int p = 0; p < 4; p++) {
                        const ulonglong2 vv = vr[p];
                        FMA2(o2[2 * p],     vv.x, pm, o2[2 * p]);
                        FMA2(o2[2 * p + 1], vv.y, pm, o2[2 * p + 1]);
                    }
                }
                #pragma unroll
                for (int p = 0; p < 8; p++) {
                    const float2 u = unpack2(o2[p]);
                    const int c0 = h * 32 + half * 16 + 2 * p;
                    af[af_addr(chnk_row + (c0 >> 3), lrow + (c0 & 3),
                               ((c0 & 4) >> 1) + ebase)] = tf32f(u.x);
                    const int c1 = c0 + 1;
                    af[af_addr(chnk_row + (c1 >> 3), lrow + (c1 & 3),
                               ((c1 & 4) >> 1) + ebase)] = tf32f(u.y);
                }
            }
        }
    }
    __syncthreads();

    // ---- P3: proj via tf32 mma. Warp owns 16 cols (2 ntiles) ----
    {
        float C[2][2][4];
        #pragma unroll
        for (int nt2 = 0; nt2 < 2; nt2++) {
            const int j0 = (wid * 2 + nt2) * 8 + qd * 2;
            const float2 bb = *(const float2*)(proj_b + j0);
            #pragma unroll
            for (int mt = 0; mt < 2; mt++) {
                C[nt2][mt][0] = bb.x; C[nt2][mt][1] = bb.y;
                C[nt2][mt][2] = bb.x; C[nt2][mt][3] = bb.y;
            }
        }
        #pragma unroll
        for (int ks2 = 0; ks2 < 8; ks2++) {
            uint32_t A[2][2][4];
            #pragma unroll
            for (int mt = 0; mt < 2; mt++)
                #pragma unroll
                for (int kk = 0; kk < 2; kk++) {
                    const float4 av = *(const float4*)(af + af_addr(mt * 16 + ks2 * 2 + kk, lane, 0));
                    A[mt][kk][0] = __float_as_uint(av.x);
                    A[mt][kk][1] = __float_as_uint(av.y);
                    A[mt][kk][2] = __float_as_uint(av.z);
                    A[mt][kk][3] = __float_as_uint(av.w);
                }
            #pragma unroll
            for (int nt2 = 0; nt2 < 2; nt2++) {
                const float4 bv = g_bproj[((wid * 2 + nt2) * 8 + ks2) * 32 + lane];
                const uint32_t b0 = __float_as_uint(bv.x), b1 = __float_as_uint(bv.y);
                const uint32_t b2 = __float_as_uint(bv.z), b3 = __float_as_uint(bv.w);
                MMA_TF32(C[nt2][0], A[0][0][0], A[0][0][1], A[0][0][2], A[0][0][3], b0, b1);
                MMA_TF32(C[nt2][1], A[1][0][0], A[1][0][1], A[1][0][2], A[1][0][3], b0, b1);
                MMA_TF32(C[nt2][0], A[0][1][0], A[0][1][1], A[0][1][2], A[0][1][3], b2, b3);
                MMA_TF32(C[nt2][1], A[1][1][0], A[1][1][1], A[1][1][2], A[1][1][3], b2, b3);
            }
        }
        float* ob = out + (size_t)b * (NTOK * DIM);
        #pragma unroll
        for (int nt2 = 0; nt2 < 2; nt2++) {
            const int j0 = (wid * 2 + nt2) * 8 + qd * 2;
            #pragma unroll
            for (int mt = 0; mt < 2; mt++) {
                const int row = mt * 16 + g;
                if (row < NTOK)
                    *(float2*)(ob + row * DIM + j0) = make_float2(C[nt2][mt][0], C[nt2][mt][1]);
                if (row + 8 < NTOK)
                    *(float2*)(ob + (row + 8) * DIM + j0) = make_float2(C[nt2][mt][2], C[nt2][mt][3]);
            }
        }
    }
}

extern "C" void kernel_launch(void* const* d_in, const int* in_sizes, int n_in,
                              void* d_out, int out_size)
{
    const float* x          = (const float*)d_in[0];
    const float* mask       = (const float*)d_in[1];
    const int*   ids_keep   = (const int*)  d_in[2];
    const float* qkv_w      = (const float*)d_in[3];
    const float* qkv_b      = (const float*)d_in[4];
    const float* proj_w     = (const float*)d_in[5];
    const float* proj_b     = (const float*)d_in[6];
    const float* bias_table = (const float*)d_in[7];
    const int*   rel_index  = (const int*)  d_in[8];

    pack_weights<<<64, 256>>>(qkv_w, proj_w);
    fill_bm<<<625, 256>>>(mask, ids_keep, bias_table, rel_index);

    const int smem_bytes = SM_FLOATS * 4;
    cudaFuncSetAttribute(win_attn_kernel,
                         cudaFuncAttributeMaxDynamicSharedMemorySize, smem_bytes);
    win_attn_kernel<<<4096, 256, smem_bytes>>>(x, qkv_b, proj_b, (float*)d_out);
}